// round 1
// baseline (speedup 1.0000x reference)
#include <cuda_runtime.h>
#include <math.h>

#define MAXN 100000
#define MAXE 1600000

// ---------------- scratch (static device arrays; no allocation) ----------------
__device__ float g_dinv[MAXN];            // deg, then rsqrt(deg)
__device__ int   g_cnt[MAXN];
__device__ int   g_cur[MAXN];
__device__ int   g_offs[MAXN + 1];
__device__ int   g_bsum[128];
__device__ int2  g_edge[MAXE];            // {src, bitcast(norm)} CSR payload
__device__ float g_A2[(size_t)MAXN * 192];// [XA(128) | h(64)] per node
__device__ float g_P[(size_t)MAXN * 192]; // [Zpre' | Rpre' | Ht_partial]
__device__ float g_W2[192 * 192];
__device__ float g_c[192];

// ---------------- small setup kernels ----------------
__global__ void k_init(int n) {
    int i = blockIdx.x * blockDim.x + threadIdx.x;
    if (i < n) { g_dinv[i] = 1.0f; g_cnt[i] = 0; g_cur[i] = 0; }
}

__global__ void k_hist(const int* __restrict__ ei, const float* __restrict__ ew, int E) {
    int e = blockIdx.x * blockDim.x + threadIdx.x;
    if (e < E) {
        int c = ei[E + e];
        atomicAdd(&g_dinv[c], ew[e]);
        atomicAdd(&g_cnt[c], 1);
    }
}

__global__ void k_dinv(int n) {
    int i = blockIdx.x * blockDim.x + threadIdx.x;
    if (i < n) g_dinv[i] = rsqrtf(g_dinv[i]);   // deg >= 1 always (self-loop)
}

__global__ void k_scanA(int n) {
    __shared__ int s[1024];
    int tid = threadIdx.x;
    int i = blockIdx.x * 1024 + tid;
    int v = (i < n) ? g_cnt[i] : 0;
    s[tid] = v; __syncthreads();
    for (int d = 1; d < 1024; d <<= 1) {
        int t = (tid >= d) ? s[tid - d] : 0;
        __syncthreads();
        s[tid] += t;
        __syncthreads();
    }
    if (i < n) g_offs[i] = s[tid] - v;          // exclusive within block
    if (tid == 1023) g_bsum[blockIdx.x] = s[1023];
}

__global__ void k_scanB(int nb, int n, int E) {
    __shared__ int s[128];
    int tid = threadIdx.x;
    int v = (tid < nb) ? g_bsum[tid] : 0;
    s[tid] = v; __syncthreads();
    for (int d = 1; d < 128; d <<= 1) {
        int t = (tid >= d) ? s[tid - d] : 0;
        __syncthreads();
        s[tid] += t;
        __syncthreads();
    }
    if (tid < nb) g_bsum[tid] = s[tid] - v;     // exclusive block offsets
    if (tid == 0) g_offs[n] = E;
}

__global__ void k_scanC(int n) {
    int i = blockIdx.x * 1024 + threadIdx.x;
    if (i < n) g_offs[i] += g_bsum[blockIdx.x];
}

__global__ void k_fill(const int* __restrict__ ei, const float* __restrict__ ew, int E) {
    int e = blockIdx.x * blockDim.x + threadIdx.x;
    if (e < E) {
        int r = ei[e];
        int c = ei[E + e];
        float nrm = g_dinv[r] * ew[e] * g_dinv[c];
        int pos = g_offs[c] + atomicAdd(&g_cur[c], 1);
        g_edge[pos] = make_int2(r, __float_as_int(nrm));
    }
}

// fold gate linears into GCN weights: W2[192,192]
__global__ void k_w2(const float* __restrict__ Wz, const float* __restrict__ Wr,
                     const float* __restrict__ Wh, const float* __restrict__ Lz,
                     const float* __restrict__ Lr, const float* __restrict__ Lh) {
    int idx = blockIdx.x * blockDim.x + threadIdx.x;
    if (idx >= 192 * 192) return;
    int k = idx / 192, j = idx % 192;
    float val;
    if (k < 128) {
        int g = j >> 6, jj = j & 63;
        const float* W = (g == 0) ? Wz : ((g == 1) ? Wr : Wh);
        const float* L = (g == 0) ? Lz : ((g == 1) ? Lr : Lh);
        float s = 0.f;
        #pragma unroll 8
        for (int m = 0; m < 64; m++) s = fmaf(W[k * 64 + m], L[m * 64 + jj], s);
        val = s;
    } else {
        int kk = k - 128;
        if (j < 64)       val = Lz[(64 + kk) * 64 + j];
        else if (j < 128) val = Lr[(64 + kk) * 64 + (j - 64)];
        else              val = 0.f;          // h*R term handled in finalize
    }
    g_W2[idx] = val;
}

__global__ void k_cbias(const float* __restrict__ bz, const float* __restrict__ br,
                        const float* __restrict__ bh, const float* __restrict__ Lz,
                        const float* __restrict__ Lr, const float* __restrict__ Lh,
                        const float* __restrict__ bLz, const float* __restrict__ bLr,
                        const float* __restrict__ bLh) {
    int j = threadIdx.x;
    if (j >= 192) return;
    int g = j >> 6, jj = j & 63;
    const float* b  = (g == 0) ? bz  : ((g == 1) ? br  : bh);
    const float* L  = (g == 0) ? Lz  : ((g == 1) ? Lr  : Lh);
    const float* bL = (g == 0) ? bLz : ((g == 1) ? bLr : bLh);
    float s = bL[jj];
    #pragma unroll 8
    for (int m = 0; m < 64; m++) s = fmaf(b[m], L[m * 64 + jj], s);
    g_c[j] = s;
}

// ---------------- aggregation: XA[i] = dinv^2 * x[i] + sum_in norm * x[src] ----------------
__global__ __launch_bounds__(256) void k_agg(const float* __restrict__ x, int n) {
    int warp = threadIdx.x >> 5, lane = threadIdx.x & 31;
    int node = blockIdx.x * 8 + warp;
    if (node >= n) return;
    const float4* xv = (const float4*)x;
    float di = g_dinv[node];
    float s = di * di;
    float4 a = xv[(size_t)node * 32 + lane];
    float4 acc = make_float4(s * a.x, s * a.y, s * a.z, s * a.w);
    int j = g_offs[node], j1 = g_offs[node + 1];
    for (; j + 1 < j1; j += 2) {
        int2 e0 = g_edge[j], e1 = g_edge[j + 1];
        float4 v0 = xv[(size_t)e0.x * 32 + lane];
        float4 v1 = xv[(size_t)e1.x * 32 + lane];
        float w0 = __int_as_float(e0.y), w1 = __int_as_float(e1.y);
        acc.x = fmaf(w0, v0.x, acc.x); acc.y = fmaf(w0, v0.y, acc.y);
        acc.z = fmaf(w0, v0.z, acc.z); acc.w = fmaf(w0, v0.w, acc.w);
        acc.x = fmaf(w1, v1.x, acc.x); acc.y = fmaf(w1, v1.y, acc.y);
        acc.z = fmaf(w1, v1.z, acc.z); acc.w = fmaf(w1, v1.w, acc.w);
    }
    if (j < j1) {
        int2 e0 = g_edge[j];
        float4 v0 = xv[(size_t)e0.x * 32 + lane];
        float w0 = __int_as_float(e0.y);
        acc.x = fmaf(w0, v0.x, acc.x); acc.y = fmaf(w0, v0.y, acc.y);
        acc.z = fmaf(w0, v0.z, acc.z); acc.w = fmaf(w0, v0.w, acc.w);
    }
    ((float4*)g_A2)[(size_t)node * 48 + lane] = acc;
}

__global__ void k_hcopy(const float* __restrict__ h, int n) {
    int i = blockIdx.x * blockDim.x + threadIdx.x;
    int total = n * 16;
    if (i < total) {
        int node = i >> 4, q = i & 15;
        ((float4*)g_A2)[(size_t)node * 48 + 32 + q] = ((const float4*)h)[i];
    }
}

// ---------------- GEMM: P[N,192] = A2[N,192] @ W2[192,192] ----------------
__global__ __launch_bounds__(256) void k_gemm(int n) {
    __shared__ float As[32][132];     // transposed A tile, padded
    __shared__ float Bs[32 * 192];
    const float* A = g_A2;
    const float* B = g_W2;
    float* C = g_P;
    int tid = threadIdx.x;
    int rowBase = blockIdx.x * 128;
    int ty = tid >> 4, tx = tid & 15;

    float acc[8][12];
    #pragma unroll
    for (int i = 0; i < 8; i++)
        #pragma unroll
        for (int jx = 0; jx < 12; jx++) acc[i][jx] = 0.f;

    for (int k0 = 0; k0 < 192; k0 += 32) {
        // stage B slice (32 x 192)
        const float4* Bg = (const float4*)(B + k0 * 192);
        float4* Bsv = (float4*)Bs;
        #pragma unroll
        for (int q = 0; q < 6; q++) Bsv[tid + q * 256] = Bg[tid + q * 256];
        // stage A slice transposed
        int m = tid >> 1, kh = (tid & 1) * 16;
        int r = rowBase + m;
        const float* Ar = A + (size_t)r * 192 + k0 + kh;
        #pragma unroll
        for (int q = 0; q < 4; q++) {
            float4 v = (r < n) ? *(const float4*)(Ar + 4 * q) : make_float4(0.f, 0.f, 0.f, 0.f);
            As[kh + 4 * q + 0][m] = v.x;
            As[kh + 4 * q + 1][m] = v.y;
            As[kh + 4 * q + 2][m] = v.z;
            As[kh + 4 * q + 3][m] = v.w;
        }
        __syncthreads();
        #pragma unroll
        for (int k = 0; k < 32; k++) {
            float a[8], b[12];
            #pragma unroll
            for (int i = 0; i < 8; i++) a[i] = As[k][ty * 8 + i];
            #pragma unroll
            for (int jx = 0; jx < 12; jx++) b[jx] = Bs[k * 192 + tx * 12 + jx];
            #pragma unroll
            for (int i = 0; i < 8; i++)
                #pragma unroll
                for (int jx = 0; jx < 12; jx++)
                    acc[i][jx] = fmaf(a[i], b[jx], acc[i][jx]);
        }
        __syncthreads();
    }
    #pragma unroll
    for (int i = 0; i < 8; i++) {
        int row = rowBase + ty * 8 + i;
        if (row < n) {
            float* Crow = C + (size_t)row * 192 + tx * 12;
            #pragma unroll
            for (int jx = 0; jx < 12; jx++) Crow[jx] = acc[i][jx];
        }
    }
}

// ---------------- finalize: gates, (h*R)@Lh_bot, GRU blend, head ----------------
__device__ __forceinline__ float sigf(float v) { return 1.f / (1.f + __expf(-v)); }

__global__ __launch_bounds__(256) void k_final(const float* __restrict__ h,
                                               const float* __restrict__ Lh,
                                               const float* __restrict__ Wo,
                                               const float* __restrict__ bo,
                                               float* __restrict__ out, int n) {
    __shared__ float Lhb[64][65];
    __shared__ float sWo[64];
    __shared__ float sc[192];
    int tid = threadIdx.x;
    for (int i = tid; i < 4096; i += 256) {
        int k = i >> 6, j = i & 63;
        Lhb[k][j] = Lh[(64 + k) * 64 + j];
    }
    if (tid < 64) sWo[tid] = Wo[tid];
    if (tid < 192) sc[tid] = g_c[tid];
    __syncthreads();

    int warp = tid >> 5, lane = tid & 31;
    int node = blockIdx.x * 8 + warp;
    if (node >= n) return;

    const float* p = g_P + (size_t)node * 192;
    float z0 = sigf(p[lane]       + sc[lane]);
    float z1 = sigf(p[lane + 32]  + sc[lane + 32]);
    float r0 = sigf(p[lane + 64]  + sc[lane + 64]);
    float r1 = sigf(p[lane + 96]  + sc[lane + 96]);
    float q0 =      p[lane + 128] + sc[lane + 128];
    float q1 =      p[lane + 160] + sc[lane + 160];

    float h0 = h[(size_t)node * 64 + lane];
    float h1 = h[(size_t)node * 64 + lane + 32];
    float v0 = h0 * r0, v1 = h1 * r1;

    float acc0 = q0, acc1 = q1;
    #pragma unroll
    for (int k = 0; k < 32; k++) {
        float vk = __shfl_sync(0xffffffffu, v0, k);
        acc0 = fmaf(vk, Lhb[k][lane], acc0);
        acc1 = fmaf(vk, Lhb[k][lane + 32], acc1);
    }
    #pragma unroll
    for (int k = 0; k < 32; k++) {
        float vk = __shfl_sync(0xffffffffu, v1, k);
        acc0 = fmaf(vk, Lhb[k + 32][lane], acc0);
        acc1 = fmaf(vk, Lhb[k + 32][lane + 32], acc1);
    }
    float t0 = tanhf(acc0), t1 = tanhf(acc1);
    float hn0 = z0 * h0 + (1.f - z0) * t0;
    float hn1 = z1 * h1 + (1.f - z1) * t1;

    out[n + (size_t)node * 64 + lane]      = hn0;
    out[n + (size_t)node * 64 + lane + 32] = hn1;

    float dot = hn0 * sWo[lane] + hn1 * sWo[lane + 32];
    #pragma unroll
    for (int o = 16; o; o >>= 1) dot += __shfl_down_sync(0xffffffffu, dot, o);
    if (lane == 0) out[node] = dot + bo[0];
}

// ---------------- launcher ----------------
extern "C" void kernel_launch(void* const* d_in, const int* in_sizes, int n_in,
                              void* d_out, int out_size) {
    const float* x   = (const float*)d_in[0];
    const int*   ei  = (const int*)  d_in[1];
    const float* ew  = (const float*)d_in[2];
    const float* h   = (const float*)d_in[3];
    const float* Wz  = (const float*)d_in[4];
    const float* bz  = (const float*)d_in[5];
    const float* Wr  = (const float*)d_in[6];
    const float* br  = (const float*)d_in[7];
    const float* Wh  = (const float*)d_in[8];
    const float* bh  = (const float*)d_in[9];
    const float* Lz  = (const float*)d_in[10];
    const float* bLz = (const float*)d_in[11];
    const float* Lr  = (const float*)d_in[12];
    const float* bLr = (const float*)d_in[13];
    const float* Lh  = (const float*)d_in[14];
    const float* bLh = (const float*)d_in[15];
    const float* Wo  = (const float*)d_in[16];
    const float* bo  = (const float*)d_in[17];
    float* out = (float*)d_out;

    int N = in_sizes[0] / 128;
    int E = in_sizes[2];
    int NB = (N + 1023) / 1024;

    k_init<<<(N + 255) / 256, 256>>>(N);
    k_hist<<<(E + 255) / 256, 256>>>(ei, ew, E);
    k_dinv<<<(N + 255) / 256, 256>>>(N);
    k_scanA<<<NB, 1024>>>(N);
    k_scanB<<<1, 128>>>(NB, N, E);
    k_scanC<<<NB, 1024>>>(N);
    k_fill<<<(E + 255) / 256, 256>>>(ei, ew, E);
    k_agg<<<(N + 7) / 8, 256>>>(x, N);
    k_hcopy<<<(N * 16 + 255) / 256, 256>>>(h, N);
    k_w2<<<(192 * 192 + 255) / 256, 256>>>(Wz, Wr, Wh, Lz, Lr, Lh);
    k_cbias<<<1, 192>>>(bz, br, bh, Lz, Lr, Lh, bLz, bLr, bLh);
    k_gemm<<<(N + 127) / 128, 256>>>(N);
    k_final<<<(N + 7) / 8, 256>>>(h, Lh, Wo, bo, out, N);
}